// round 15
// baseline (speedup 1.0000x reference)
#include <cuda_runtime.h>
#include <cuda_bf16.h>

#define DIMF 128
#define HIDF 256
#define TM   128
#define MAXBLK 1024
#define H1S  264            // h1/xs row stride (bf16), conflict-free
#define BSTR 40             // B chunk row stride (bf16), conflict-free
#define CHUNKB 40960        // 512 rows * 40 bf16 * 2B

__device__ float g_xi[DIMF];
__device__ float g_c1[HIDF];
__device__ float g_partials[MAXBLK * HIDF];
__device__ float g_p2[32 * HIDF];
__device__ float g_h[HIDF];
// chunk-blocked, padded weight images: [chunk][512 rows][40 bf16]
__device__ __align__(16) __nv_bfloat16 gWaP[4 * 512 * BSTR];
__device__ __align__(16) __nv_bfloat16 gWeP[8 * 512 * BSTR];

__device__ __forceinline__ unsigned smem_u32(const void* p) {
    unsigned a;
    asm("{ .reg .u64 t; cvta.to.shared.u64 t, %1; cvt.u32.u64 %0, t; }" : "=r"(a) : "l"(p));
    return a;
}
__device__ __forceinline__ unsigned packpair(float a, float b) {
    return (unsigned)__bfloat16_as_ushort(__float2bfloat16_rn(a)) |
           ((unsigned)__bfloat16_as_ushort(__float2bfloat16_rn(b)) << 16);
}
__device__ __forceinline__ void split2(float2 p, unsigned& hi, unsigned& lo) {
    __nv_bfloat16 h0 = __float2bfloat16_rn(p.x), h1 = __float2bfloat16_rn(p.y);
    hi = (unsigned)__bfloat16_as_ushort(h0) | ((unsigned)__bfloat16_as_ushort(h1) << 16);
    lo = packpair(p.x - __bfloat162float(h0), p.y - __bfloat162float(h1));
}
#define MMA(c, a, b0_, b1_)                                                     \
    asm volatile("mma.sync.aligned.m16n8k16.row.col.f32.bf16.bf16.f32 "         \
        "{%0,%1,%2,%3},{%4,%5,%6,%7},{%8,%9},{%0,%1,%2,%3};"                    \
        : "+f"((c)[0]), "+f"((c)[1]), "+f"((c)[2]), "+f"((c)[3])                \
        : "r"((a)[0]), "r"((a)[1]), "r"((a)[2]), "r"((a)[3]), "r"(b0_), "r"(b1_))
#define LDM4(r, addr)                                                           \
    asm volatile("ldmatrix.sync.aligned.m8n8.x4.shared.b16 {%0,%1,%2,%3}, [%4];" \
        : "=r"((r)[0]), "=r"((r)[1]), "=r"((r)[2]), "=r"((r)[3]) : "r"(addr))
#define MBI(a, c) asm volatile("mbarrier.init.shared.b64 [%0], %1;" :: "r"(a), "r"(c) : "memory")
#define MBTX(a, b) asm volatile("mbarrier.arrive.expect_tx.shared.b64 _, [%0], %1;" :: "r"(a), "r"(b) : "memory")
#define MBARR(a)   asm volatile("mbarrier.arrive.shared.b64 _, [%0];" :: "r"(a) : "memory")
#define MBWAIT(a, ph) do {                                                    \
    unsigned _m = (a), _p = (ph), _d;                                         \
    asm volatile("{ .reg .pred p; mbarrier.try_wait.parity.acquire.cta.shared::cta.b64 p, [%1], %2;" \
                 " selp.b32 %0, 1, 0, p; }" : "=r"(_d) : "r"(_m), "r"(_p) : "memory"); \
    if (!_d) asm volatile("{ .reg .pred P1; WL%=:"                            \
        " mbarrier.try_wait.parity.acquire.cta.shared::cta.b64 P1, [%0], %1, 0x989680;" \
        " @P1 bra.uni WD%=; bra.uni WL%=; WD%=: }" :: "r"(_m), "r"(_p) : "memory"); \
    } while (0)
__device__ __forceinline__ void bulk_g2s(unsigned dst, const void* src,
                                         unsigned bytes, unsigned mbar) {
    asm volatile("cp.async.bulk.shared::cluster.global.mbarrier::complete_tx::bytes [%0], [%1], %2, [%3];"
                 :: "r"(dst), "l"(src), "r"(bytes), "r"(mbar) : "memory");
}
__device__ __forceinline__ const __nv_bfloat16* chunk_src(int gc) {
    return (gc < 4) ? (gWaP + (size_t)gc * 20480) : (gWeP + (size_t)(gc - 4) * 20480);
}

// ---- prep: padded chunk-blocked bf16 hi/lo weight images + xi/c1 ------------
__global__ void prep_kernel(const float* __restrict__ x, const int* __restrict__ ip,
                            const float* __restrict__ Wn2e, const float* __restrict__ bn2e,
                            const float* __restrict__ We2e) {
    int t = threadIdx.x;
    if (blockIdx.x == 480) {    // xi + c1
        __shared__ float xi[DIMF];
        int idx = ip[0];
        if (t < DIMF) { float v = x[idx * DIMF + t]; xi[t] = v; g_xi[t] = v; }
        __syncthreads();
        int w = t >> 5, lane = t & 31;
        for (int it = 0; it < 32; ++it) {
            int j = w * 32 + it;
            const float* wr = Wn2e + j * 256 + DIMF;
            float acc = 0.0f;
            #pragma unroll
            for (int i = 0; i < 4; ++i) acc += wr[lane + 32 * i] * xi[lane + 32 * i];
            #pragma unroll
            for (int o = 16; o >= 1; o >>= 1) acc += __shfl_down_sync(0xffffffffu, acc, o);
            if (lane == 0) g_c1[j] = acc + bn2e[j];
        }
        return;
    }
    int gid = blockIdx.x * 256 + t;
    int gc = gid / 10240;
    int local = gid - gc * 10240;
    int row = local / 20;
    int kpair = local - row * 20;
    bool isWa = gc < 4;
    int chunk = isWa ? gc : gc - 4;
    __nv_bfloat16* dst = (isWa ? gWaP : gWeP) + ((size_t)(chunk * 512 + row)) * BSTR + kpair * 2;
    if (kpair >= 16) { *(unsigned*)dst = 0u; return; }
    int n = (row < 256) ? row : row - 256;
    int k = chunk * 32 + kpair * 2;
    const float* W = isWa ? Wn2e : We2e;
    float2 p = make_float2(W[n * 256 + k], W[n * 256 + k + 1]);
    unsigned hi, lo;
    split2(p, hi, lo);
    *(unsigned*)dst = (row < 256) ? hi : lo;
}

// ---- main: HMMA split-2 both GEMMs, depth-3 bulk-DMA pipeline ---------------
__global__ void __launch_bounds__(512, 1)
main_kernel(const float* __restrict__ x, const float* __restrict__ adj,
            const float* __restrict__ be2e, int N) {
    extern __shared__ __align__(16) __nv_bfloat16 dsm[];
    __nv_bfloat16* h1 = dsm;                         // [128][H1S]; also xs (hi only)
    __nv_bfloat16* Bs = dsm + 128 * H1S;             // [3][512][BSTR]
    __shared__ float c1s[HIDF], b2s[HIDF], adjs[TM], sred[512];
    __shared__ __align__(8) unsigned long long mbars[6];  // full0-2 used0-2

    const int tid = threadIdx.x;
    const int w = tid >> 5, lane = tid & 31;
    const int g = lane >> 2, t = lane & 3;
    const int wn = w >> 1, wm = w & 1;
    const int nb = wn * 32;
    const int mbase = wm * 64;
    const int rbase = blockIdx.x * TM;

    const unsigned bs_u32 = smem_u32(Bs);
    const unsigned h1_u32 = smem_u32(h1);
    const unsigned mb = smem_u32(mbars);

    if (tid == 0) {
        MBI(mb, 1); MBI(mb + 8, 1); MBI(mb + 16, 1);
        MBI(mb + 24, 16); MBI(mb + 32, 16); MBI(mb + 40, 16);
        MBTX(mb, CHUNKB);      bulk_g2s(bs_u32,              gWaP,         CHUNKB, mb);
        MBTX(mb + 8, CHUNKB);  bulk_g2s(bs_u32 + CHUNKB,     gWaP + 20480, CHUNKB, mb + 8);
        MBTX(mb + 16, CHUNKB); bulk_g2s(bs_u32 + 2 * CHUNKB, gWaP + 40960, CHUNKB, mb + 16);
    }

    if (tid < HIDF) { c1s[tid] = g_c1[tid]; b2s[tid] = be2e[tid]; }
    else if (tid < HIDF + TM) {
        int lt = tid - HIDF;
        int r = rbase + lt;
        adjs[lt] = (r < N) ? adj[r] : 0.0f;
    }

    const int rr = lane & 7, q = lane >> 3;
    const unsigned arow_off = (unsigned)(((q & 1) << 3) + rr) * (H1S * 2);
    const unsigned akoff = (unsigned)((q >> 1) << 3) * 2;
    const int bsel = lane >> 3, bln = lane & 7;
    const unsigned b_off = (unsigned)((((bsel >> 1) << 3) + bln) * BSTR + ((bsel & 1) << 3)) * 2;

    float acc[4][4][4];
    unsigned Bh0[4], Bh1[4], Bl0[4], Bl1[4];

    // ---- stage x: bf16 hi plane only -> xs (aliased with h1) ----
    {
        int r = tid >> 2;
        int cq = (tid & 3) << 5;
        int row = rbase + r;
        float f[32];
        if (row < N) {
            const float4* xr = (const float4*)(x + (size_t)row * DIMF + cq);
            #pragma unroll
            for (int qq = 0; qq < 8; ++qq) {
                float4 v = xr[qq];
                f[4*qq] = v.x; f[4*qq+1] = v.y; f[4*qq+2] = v.z; f[4*qq+3] = v.w;
            }
        } else {
            #pragma unroll
            for (int qq = 0; qq < 32; ++qq) f[qq] = 0.0f;
        }
        #pragma unroll
        for (int p = 0; p < 8; ++p) {
            int col = cq + 4 * p;
            *(uint2*)(h1 + (size_t)r * H1S + col) =
                make_uint2(packpair(f[4*p], f[4*p+1]), packpair(f[4*p+2], f[4*p+3]));
        }
    }
    __syncthreads();   // xs staged, mbars init'd, c1s/adjs ready

    // depth-3 pipeline: buffer = gc%3, parity = (gc/3)&1, prefetch gc+3
    #define CHUNK_WAIT(gc_)                                                     \
        MBWAIT(mb + (unsigned)(((gc_) % 3) * 8), ((gc_) / 3) & 1)
    #define CHUNK_DONE(gc_)                                                     \
    {                                                                           \
        if (lane == 0) MBARR(mb + 24 + (unsigned)(((gc_) % 3) * 8));            \
        if (tid == 0 && (gc_) + 3 < 12) {                                       \
            int nx = (gc_) + 3;                                                 \
            MBWAIT(mb + 24 + (unsigned)(((gc_) % 3) * 8), ((gc_) / 3) & 1);     \
            unsigned fb = mb + (unsigned)(((gc_) % 3) * 8);                     \
            MBTX(fb, CHUNKB);                                                   \
            bulk_g2s(bs_u32 + (unsigned)(((gc_) % 3) * CHUNKB), chunk_src(nx), CHUNKB, fb); \
        }                                                                       \
    }
    #define LOAD_B(bufb_, kk_)                                                  \
    {                                                                           \
        const unsigned bb = (bufb_) + (unsigned)((nb * BSTR + (kk_) * 16) * 2) + b_off; \
        { unsigned r4[4]; LDM4(r4, bb);                                         \
          Bh0[0]=r4[0]; Bh1[0]=r4[1]; Bh0[1]=r4[2]; Bh1[1]=r4[3]; }             \
        { unsigned r4[4]; LDM4(r4, bb + 16 * BSTR * 2);                         \
          Bh0[2]=r4[0]; Bh1[2]=r4[1]; Bh0[3]=r4[2]; Bh1[3]=r4[3]; }             \
        { unsigned r4[4]; LDM4(r4, bb + 256 * BSTR * 2);                        \
          Bl0[0]=r4[0]; Bl1[0]=r4[1]; Bl0[1]=r4[2]; Bl1[1]=r4[3]; }             \
        { unsigned r4[4]; LDM4(r4, bb + (256 + 16) * BSTR * 2);                 \
          Bl0[2]=r4[0]; Bl1[2]=r4[1]; Bl0[3]=r4[2]; Bl1[3]=r4[3]; }             \
    }
    #define GEMM_CHUNK(gc_, kbase_)                                             \
    {                                                                           \
        CHUNK_WAIT(gc_);                                                        \
        const unsigned bufb = bs_u32 + (unsigned)(((gc_) % 3) * CHUNKB);        \
        _Pragma("unroll")                                                       \
        for (int kk = 0; kk < 2; ++kk) {                                        \
            const int kg = (kbase_) + kk * 16;                                  \
            LOAD_B(bufb, kk);                                                   \
            _Pragma("unroll")                                                   \
            for (int mt = 0; mt < 4; ++mt) {                                    \
                unsigned base = h1_u32 + (unsigned)(mbase + mt * 16) * (H1S * 2) \
                                + arow_off + (unsigned)kg * 2 + akoff;          \
                unsigned ah[4];                                                 \
                LDM4(ah, base);                                                 \
                _Pragma("unroll")                                               \
                for (int nt = 0; nt < 4; ++nt) MMA(acc[mt][nt], ah, Bh0[nt], Bh1[nt]); \
                _Pragma("unroll")                                               \
                for (int nt = 0; nt < 4; ++nt) MMA(acc[mt][nt], ah, Bl0[nt], Bl1[nt]); \
            }                                                                   \
        }                                                                       \
        CHUNK_DONE(gc_);                                                        \
    }

    // =========================== GEMM 1 (gc 0..3) ===========================
    #pragma unroll
    for (int a = 0; a < 4; ++a)
        #pragma unroll
        for (int b = 0; b < 4; ++b)
            #pragma unroll
            for (int i = 0; i < 4; ++i) acc[a][b][i] = 0.0f;

    for (int gc = 0; gc < 4; ++gc)
        GEMM_CHUNK(gc, gc * 32);

    __syncthreads();   // all GEMM1 xs reads done before h1 overwrites xs
    // epilogue 1: relu(acc + c1) -> bf16 hi -> h1
    #pragma unroll
    for (int mt = 0; mt < 4; ++mt) {
        int lr0 = mbase + mt * 16 + g;
        #pragma unroll
        for (int nt = 0; nt < 4; ++nt) {
            int col = nb + nt * 8 + 2 * t;
            float b0 = c1s[col], b1 = c1s[col + 1];
            float v0 = fmaxf(acc[mt][nt][0] + b0, 0.0f);
            float v1 = fmaxf(acc[mt][nt][1] + b1, 0.0f);
            float v2 = fmaxf(acc[mt][nt][2] + b0, 0.0f);
            float v3 = fmaxf(acc[mt][nt][3] + b1, 0.0f);
            *(unsigned*)(h1 + (size_t)lr0 * H1S + col)       = packpair(v0, v1);
            *(unsigned*)(h1 + (size_t)(lr0 + 8) * H1S + col) = packpair(v2, v3);
        }
    }
    __syncthreads();   // h1 complete before GEMM2 reads it

    // =========================== GEMM 2 (gc 4..11) ==========================
    #pragma unroll
    for (int a = 0; a < 4; ++a)
        #pragma unroll
        for (int b = 0; b < 4; ++b)
            #pragma unroll
            for (int i = 0; i < 4; ++i) acc[a][b][i] = 0.0f;

    for (int gc = 4; gc < 12; ++gc)
        GEMM_CHUNK(gc, (gc - 4) * 32);

    // epilogue 2: relu(acc + b2) * adj, column sums over this warp's 64 rows
    float colsum[4][2];
    #pragma unroll
    for (int nt = 0; nt < 4; ++nt) { colsum[nt][0] = 0.0f; colsum[nt][1] = 0.0f; }
    #pragma unroll
    for (int mt = 0; mt < 4; ++mt) {
        int lr0 = mbase + mt * 16 + g;
        float a0 = adjs[lr0], a8 = adjs[lr0 + 8];
        #pragma unroll
        for (int nt = 0; nt < 4; ++nt) {
            int col = nb + nt * 8 + 2 * t;
            float b0 = b2s[col], b1 = b2s[col + 1];
            colsum[nt][0] += fmaxf(acc[mt][nt][0] + b0, 0.0f) * a0
                           + fmaxf(acc[mt][nt][2] + b0, 0.0f) * a8;
            colsum[nt][1] += fmaxf(acc[mt][nt][1] + b1, 0.0f) * a0
                           + fmaxf(acc[mt][nt][3] + b1, 0.0f) * a8;
        }
    }
    #pragma unroll
    for (int nt = 0; nt < 4; ++nt) {
        #pragma unroll
        for (int j = 0; j < 2; ++j) {
            float v = colsum[nt][j];
            v += __shfl_down_sync(0xffffffffu, v, 16);
            v += __shfl_down_sync(0xffffffffu, v, 8);
            v += __shfl_down_sync(0xffffffffu, v, 4);
            if (lane < 4)
                sred[wm * 256 + nb + nt * 8 + 2 * lane + j] = v;
        }
    }
    __syncthreads();   // both wm halves in sred
    if (tid < HIDF)
        g_partials[(size_t)blockIdx.x * HIDF + tid] = sred[tid] + sred[256 + tid];
}

// ---- parallel tail: 32-way partial reduce, h MLP, output MLP ----------------
__global__ void red_kernel(int R) {
    int t = threadIdx.x, b = blockIdx.x;
    float s = 0.0f;
    for (int r = b; r < R; r += 32) s += g_partials[(size_t)r * HIDF + t];
    g_p2[b * HIDF + t] = s;
}
__global__ void h_kernel(const float* __restrict__ We2n, const float* __restrict__ be2n) {
    __shared__ float s[HIDF];
    int t = threadIdx.x, w = t >> 5, lane = t & 31;
    float a = 0.0f;
    #pragma unroll
    for (int b = 0; b < 32; ++b) a += g_p2[b * HIDF + t];
    s[t] = a;
    __syncthreads();
    int row = blockIdx.x * 8 + w;
    const float* wr = We2n + row * HIDF;
    float acc = 0.0f;
    #pragma unroll
    for (int i = 0; i < 8; ++i) acc += wr[lane + 32 * i] * s[lane + 32 * i];
    #pragma unroll
    for (int o = 16; o >= 1; o >>= 1) acc += __shfl_down_sync(0xffffffffu, acc, o);
    if (lane == 0) g_h[row] = acc + be2n[row];
}
__global__ void final_kernel(const float* __restrict__ Wout, const float* __restrict__ bout,
                             float* __restrict__ out) {
    __shared__ float v[DIMF + HIDF];
    int t = threadIdx.x, w = t >> 5, lane = t & 31;
    for (int i = t; i < DIMF + HIDF; i += 256)
        v[i] = (i < DIMF) ? g_xi[i] : g_h[i - DIMF];
    __syncthreads();
    #pragma unroll
    for (int it = 0; it < 4; ++it) {
        int row = blockIdx.x * 32 + w * 4 + it;
        const float* wr = Wout + row * (DIMF + HIDF);
        float acc = 0.0f;
        #pragma unroll
        for (int i = 0; i < 12; ++i) acc += wr[lane + 32 * i] * v[lane + 32 * i];
        #pragma unroll
        for (int o = 16; o >= 1; o >>= 1) acc += __shfl_down_sync(0xffffffffu, acc, o);
        if (lane == 0) out[row] = v[row] + acc + bout[row];
    }
}

extern "C" void kernel_launch(void* const* d_in, const int* in_sizes, int n_in,
                              void* d_out, int out_size) {
    const float* x    = (const float*)d_in[0];
    const float* adj  = (const float*)d_in[1];
    const int*   ip   = (const int*)  d_in[2];
    const float* Wn2e = (const float*)d_in[3];
    const float* bn2e = (const float*)d_in[4];
    const float* We2e = (const float*)d_in[5];
    const float* be2e = (const float*)d_in[6];
    const float* We2n = (const float*)d_in[7];
    const float* be2n = (const float*)d_in[8];
    const float* Wout = (const float*)d_in[9];
    const float* bout = (const float*)d_in[10];
    float* out = (float*)d_out;

    const int N = in_sizes[1];
    const int nblk = (N + TM - 1) / TM;
    const int dyn = (128 * H1S + 3 * 512 * BSTR) * 2;   // 190,464 bytes
    cudaFuncSetAttribute(main_kernel, cudaFuncAttributeMaxDynamicSharedMemorySize, dyn);

    prep_kernel<<<481, 256>>>(x, ip, Wn2e, bn2e, We2e);
    main_kernel<<<nblk, 512, dyn>>>(x, adj, be2e, N);
    red_kernel<<<32, 256>>>(nblk);
    h_kernel<<<32, 256>>>(We2n, be2n);
    final_kernel<<<4, 256>>>(Wout, bout, out);
}

// round 16
// speedup vs baseline: 1.0250x; 1.0250x over previous
#include <cuda_runtime.h>
#include <cuda_bf16.h>

#define DIMF 128
#define HIDF 256
#define TM   128
#define MAXBLK 1024
#define H1S  264            // h1/xs row stride (bf16), conflict-free
#define BSTR 40             // B chunk row stride (bf16), conflict-free
#define CHUNKB 40960        // 512 rows * 40 bf16 * 2B

__device__ float g_xi[DIMF];
__device__ float g_c1[HIDF];
__device__ float g_partials[MAXBLK * HIDF];
__device__ float g_p2[32 * HIDF];
__device__ float g_h[HIDF];
// chunk-blocked, padded weight images: [chunk][512 rows][40 bf16]
__device__ __align__(16) __nv_bfloat16 gWaP[4 * 512 * BSTR];
__device__ __align__(16) __nv_bfloat16 gWeP[8 * 512 * BSTR];

__device__ __forceinline__ unsigned smem_u32(const void* p) {
    unsigned a;
    asm("{ .reg .u64 t; cvta.to.shared.u64 t, %1; cvt.u32.u64 %0, t; }" : "=r"(a) : "l"(p));
    return a;
}
__device__ __forceinline__ unsigned packpair(float a, float b) {
    return (unsigned)__bfloat16_as_ushort(__float2bfloat16_rn(a)) |
           ((unsigned)__bfloat16_as_ushort(__float2bfloat16_rn(b)) << 16);
}
__device__ __forceinline__ void split2(float2 p, unsigned& hi, unsigned& lo) {
    __nv_bfloat16 h0 = __float2bfloat16_rn(p.x), h1 = __float2bfloat16_rn(p.y);
    hi = (unsigned)__bfloat16_as_ushort(h0) | ((unsigned)__bfloat16_as_ushort(h1) << 16);
    lo = packpair(p.x - __bfloat162float(h0), p.y - __bfloat162float(h1));
}
#define MMA(c, a, b0_, b1_)                                                     \
    asm volatile("mma.sync.aligned.m16n8k16.row.col.f32.bf16.bf16.f32 "         \
        "{%0,%1,%2,%3},{%4,%5,%6,%7},{%8,%9},{%0,%1,%2,%3};"                    \
        : "+f"((c)[0]), "+f"((c)[1]), "+f"((c)[2]), "+f"((c)[3])                \
        : "r"((a)[0]), "r"((a)[1]), "r"((a)[2]), "r"((a)[3]), "r"(b0_), "r"(b1_))
#define LDM4(r, addr)                                                           \
    asm volatile("ldmatrix.sync.aligned.m8n8.x4.shared.b16 {%0,%1,%2,%3}, [%4];" \
        : "=r"((r)[0]), "=r"((r)[1]), "=r"((r)[2]), "=r"((r)[3]) : "r"(addr))
#define MBI(a, c) asm volatile("mbarrier.init.shared.b64 [%0], %1;" :: "r"(a), "r"(c) : "memory")
#define MBTX(a, b) asm volatile("mbarrier.arrive.expect_tx.shared.b64 _, [%0], %1;" :: "r"(a), "r"(b) : "memory")
#define MBARR(a)   asm volatile("mbarrier.arrive.shared.b64 _, [%0];" :: "r"(a) : "memory")
#define MBWAIT(a, ph) do {                                                    \
    unsigned _m = (a), _p = (ph), _d;                                         \
    asm volatile("{ .reg .pred p; mbarrier.try_wait.parity.acquire.cta.shared::cta.b64 p, [%1], %2;" \
                 " selp.b32 %0, 1, 0, p; }" : "=r"(_d) : "r"(_m), "r"(_p) : "memory"); \
    if (!_d) asm volatile("{ .reg .pred P1; WL%=:"                            \
        " mbarrier.try_wait.parity.acquire.cta.shared::cta.b64 P1, [%0], %1, 0x989680;" \
        " @P1 bra.uni WD%=; bra.uni WL%=; WD%=: }" :: "r"(_m), "r"(_p) : "memory"); \
    } while (0)
__device__ __forceinline__ void bulk_g2s(unsigned dst, const void* src,
                                         unsigned bytes, unsigned mbar) {
    asm volatile("cp.async.bulk.shared::cluster.global.mbarrier::complete_tx::bytes [%0], [%1], %2, [%3];"
                 :: "r"(dst), "l"(src), "r"(bytes), "r"(mbar) : "memory");
}
__device__ __forceinline__ const __nv_bfloat16* chunk_src(int gc) {
    return (gc < 4) ? (gWaP + (size_t)gc * 20480) : (gWeP + (size_t)(gc - 4) * 20480);
}

// ---- prep: padded chunk-blocked bf16 hi/lo weight images + xi/c1 ------------
__global__ void prep_kernel(const float* __restrict__ x, const int* __restrict__ ip,
                            const float* __restrict__ Wn2e, const float* __restrict__ bn2e,
                            const float* __restrict__ We2e) {
    int t = threadIdx.x;
    if (blockIdx.x == 480) {    // xi + c1
        __shared__ float xi[DIMF];
        int idx = ip[0];
        if (t < DIMF) { float v = x[idx * DIMF + t]; xi[t] = v; g_xi[t] = v; }
        __syncthreads();
        int w = t >> 5, lane = t & 31;
        for (int it = 0; it < 32; ++it) {
            int j = w * 32 + it;
            const float* wr = Wn2e + j * 256 + DIMF;
            float acc = 0.0f;
            #pragma unroll
            for (int i = 0; i < 4; ++i) acc += wr[lane + 32 * i] * xi[lane + 32 * i];
            #pragma unroll
            for (int o = 16; o >= 1; o >>= 1) acc += __shfl_down_sync(0xffffffffu, acc, o);
            if (lane == 0) g_c1[j] = acc + bn2e[j];
        }
        return;
    }
    int gid = blockIdx.x * 256 + t;
    int gc = gid / 10240;
    int local = gid - gc * 10240;
    int row = local / 20;
    int kpair = local - row * 20;
    bool isWa = gc < 4;
    int chunk = isWa ? gc : gc - 4;
    __nv_bfloat16* dst = (isWa ? gWaP : gWeP) + ((size_t)(chunk * 512 + row)) * BSTR + kpair * 2;
    if (kpair >= 16) { *(unsigned*)dst = 0u; return; }
    int n = (row < 256) ? row : row - 256;
    int k = chunk * 32 + kpair * 2;
    const float* W = isWa ? Wn2e : We2e;
    float2 p = make_float2(W[n * 256 + k], W[n * 256 + k + 1]);
    unsigned hi, lo;
    split2(p, hi, lo);
    *(unsigned*)dst = (row < 256) ? hi : lo;
}

// ---- main: HMMA split-2 both GEMMs, depth-2 bulk-DMA pipeline ---------------
__global__ void __launch_bounds__(512, 1)
main_kernel(const float* __restrict__ x, const float* __restrict__ adj,
            const float* __restrict__ be2e, int N) {
    extern __shared__ __align__(16) __nv_bfloat16 dsm[];
    __nv_bfloat16* h1 = dsm;                         // [128][H1S]; also xs (hi only)
    __nv_bfloat16* Bs = dsm + 128 * H1S;             // [2][512][BSTR]
    __shared__ float c1s[HIDF], b2s[HIDF], adjs[TM], sred[512];
    __shared__ __align__(8) unsigned long long mbars[4];  // full0 full1 used0 used1

    const int tid = threadIdx.x;
    const int w = tid >> 5, lane = tid & 31;
    const int g = lane >> 2, t = lane & 3;
    const int wn = w >> 1, wm = w & 1;
    const int nb = wn * 32;
    const int mbase = wm * 64;
    const int rbase = blockIdx.x * TM;

    const unsigned bs_u32 = smem_u32(Bs);
    const unsigned h1_u32 = smem_u32(h1);
    const unsigned mb = smem_u32(mbars);

    if (tid == 0) {
        MBI(mb, 1); MBI(mb + 8, 1); MBI(mb + 16, 16); MBI(mb + 24, 16);
        MBTX(mb, CHUNKB);     bulk_g2s(bs_u32,          gWaP,         CHUNKB, mb);
        MBTX(mb + 8, CHUNKB); bulk_g2s(bs_u32 + CHUNKB, gWaP + 20480, CHUNKB, mb + 8);
    }

    if (tid < HIDF) { c1s[tid] = g_c1[tid]; b2s[tid] = be2e[tid]; }
    else if (tid < HIDF + TM) {
        int lt = tid - HIDF;
        int r = rbase + lt;
        adjs[lt] = (r < N) ? adj[r] : 0.0f;
    }

    const int rr = lane & 7, q = lane >> 3;
    const unsigned arow_off = (unsigned)(((q & 1) << 3) + rr) * (H1S * 2);
    const unsigned akoff = (unsigned)((q >> 1) << 3) * 2;
    const int bsel = lane >> 3, bln = lane & 7;
    const unsigned b_off = (unsigned)((((bsel >> 1) << 3) + bln) * BSTR + ((bsel & 1) << 3)) * 2;

    float acc[4][4][4];
    unsigned Bh0[4], Bh1[4], Bl0[4], Bl1[4];

    // ---- stage x: bf16 hi plane only -> xs (aliased with h1) ----
    {
        int r = tid >> 2;
        int cq = (tid & 3) << 5;
        int row = rbase + r;
        float f[32];
        if (row < N) {
            const float4* xr = (const float4*)(x + (size_t)row * DIMF + cq);
            #pragma unroll
            for (int qq = 0; qq < 8; ++qq) {
                float4 v = xr[qq];
                f[4*qq] = v.x; f[4*qq+1] = v.y; f[4*qq+2] = v.z; f[4*qq+3] = v.w;
            }
        } else {
            #pragma unroll
            for (int qq = 0; qq < 32; ++qq) f[qq] = 0.0f;
        }
        #pragma unroll
        for (int p = 0; p < 8; ++p) {
            int col = cq + 4 * p;
            *(uint2*)(h1 + (size_t)r * H1S + col) =
                make_uint2(packpair(f[4*p], f[4*p+1]), packpair(f[4*p+2], f[4*p+3]));
        }
    }
    __syncthreads();   // xs staged, mbars init'd, c1s/adjs ready

    #define CHUNK_WAIT(gc_)                                                     \
        MBWAIT(mb + (unsigned)(((gc_) & 1) * 8), ((gc_) >> 1) & 1)
    #define CHUNK_DONE(gc_)                                                     \
    {                                                                           \
        if (lane == 0) MBARR(mb + 16 + (unsigned)(((gc_) & 1) * 8));            \
        if (tid == 0 && (gc_) + 2 < 12) {                                       \
            int nx = (gc_) + 2;                                                 \
            MBWAIT(mb + 16 + (unsigned)(((gc_) & 1) * 8), ((gc_) >> 1) & 1);    \
            unsigned fb = mb + (unsigned)((nx & 1) * 8);                        \
            MBTX(fb, CHUNKB);                                                   \
            bulk_g2s(bs_u32 + (unsigned)((nx & 1) * CHUNKB), chunk_src(nx), CHUNKB, fb); \
        }                                                                       \
    }
    #define LOAD_B(bufb_, kk_)                                                  \
    {                                                                           \
        const unsigned bb = (bufb_) + (unsigned)((nb * BSTR + (kk_) * 16) * 2) + b_off; \
        { unsigned r4[4]; LDM4(r4, bb);                                         \
          Bh0[0]=r4[0]; Bh1[0]=r4[1]; Bh0[1]=r4[2]; Bh1[1]=r4[3]; }             \
        { unsigned r4[4]; LDM4(r4, bb + 16 * BSTR * 2);                         \
          Bh0[2]=r4[0]; Bh1[2]=r4[1]; Bh0[3]=r4[2]; Bh1[3]=r4[3]; }             \
        { unsigned r4[4]; LDM4(r4, bb + 256 * BSTR * 2);                        \
          Bl0[0]=r4[0]; Bl1[0]=r4[1]; Bl0[1]=r4[2]; Bl1[1]=r4[3]; }             \
        { unsigned r4[4]; LDM4(r4, bb + (256 + 16) * BSTR * 2);                 \
          Bl0[2]=r4[0]; Bl1[2]=r4[1]; Bl0[3]=r4[2]; Bl1[3]=r4[3]; }             \
    }
    #define GEMM_CHUNK(gc_, kbase_)                                             \
    {                                                                           \
        CHUNK_WAIT(gc_);                                                        \
        const unsigned bufb = bs_u32 + (unsigned)(((gc_) & 1) * CHUNKB);        \
        _Pragma("unroll")                                                       \
        for (int kk = 0; kk < 2; ++kk) {                                        \
            const int kg = (kbase_) + kk * 16;                                  \
            LOAD_B(bufb, kk);                                                   \
            _Pragma("unroll")                                                   \
            for (int mt = 0; mt < 4; ++mt) {                                    \
                unsigned base = h1_u32 + (unsigned)(mbase + mt * 16) * (H1S * 2) \
                                + arow_off + (unsigned)kg * 2 + akoff;          \
                unsigned ah[4];                                                 \
                LDM4(ah, base);                                                 \
                _Pragma("unroll")                                               \
                for (int nt = 0; nt < 4; ++nt) MMA(acc[mt][nt], ah, Bh0[nt], Bh1[nt]); \
                _Pragma("unroll")                                               \
                for (int nt = 0; nt < 4; ++nt) MMA(acc[mt][nt], ah, Bl0[nt], Bl1[nt]); \
            }                                                                   \
        }                                                                       \
        CHUNK_DONE(gc_);                                                        \
    }

    // =========================== GEMM 1 (gc 0..3) ===========================
    #pragma unroll
    for (int a = 0; a < 4; ++a)
        #pragma unroll
        for (int b = 0; b < 4; ++b)
            #pragma unroll
            for (int i = 0; i < 4; ++i) acc[a][b][i] = 0.0f;

    for (int gc = 0; gc < 4; ++gc)
        GEMM_CHUNK(gc, gc * 32);

    __syncthreads();   // all GEMM1 xs reads done before h1 overwrites xs
    // epilogue 1: relu(acc + c1) -> bf16 hi -> h1
    #pragma unroll
    for (int mt = 0; mt < 4; ++mt) {
        int lr0 = mbase + mt * 16 + g;
        #pragma unroll
        for (int nt = 0; nt < 4; ++nt) {
            int col = nb + nt * 8 + 2 * t;
            float b0 = c1s[col], b1 = c1s[col + 1];
            float v0 = fmaxf(acc[mt][nt][0] + b0, 0.0f);
            float v1 = fmaxf(acc[mt][nt][1] + b1, 0.0f);
            float v2 = fmaxf(acc[mt][nt][2] + b0, 0.0f);
            float v3 = fmaxf(acc[mt][nt][3] + b1, 0.0f);
            *(unsigned*)(h1 + (size_t)lr0 * H1S + col)       = packpair(v0, v1);
            *(unsigned*)(h1 + (size_t)(lr0 + 8) * H1S + col) = packpair(v2, v3);
        }
    }
    __syncthreads();   // h1 complete before GEMM2 reads it

    // =========================== GEMM 2 (gc 4..11) ==========================
    #pragma unroll
    for (int a = 0; a < 4; ++a)
        #pragma unroll
        for (int b = 0; b < 4; ++b)
            #pragma unroll
            for (int i = 0; i < 4; ++i) acc[a][b][i] = 0.0f;

    for (int gc = 4; gc < 12; ++gc)
        GEMM_CHUNK(gc, (gc - 4) * 32);

    // epilogue 2: relu(acc + b2) * adj, column sums over this warp's 64 rows
    float colsum[4][2];
    #pragma unroll
    for (int nt = 0; nt < 4; ++nt) { colsum[nt][0] = 0.0f; colsum[nt][1] = 0.0f; }
    #pragma unroll
    for (int mt = 0; mt < 4; ++mt) {
        int lr0 = mbase + mt * 16 + g;
        float a0 = adjs[lr0], a8 = adjs[lr0 + 8];
        #pragma unroll
        for (int nt = 0; nt < 4; ++nt) {
            int col = nb + nt * 8 + 2 * t;
            float b0 = b2s[col], b1 = b2s[col + 1];
            colsum[nt][0] += fmaxf(acc[mt][nt][0] + b0, 0.0f) * a0
                           + fmaxf(acc[mt][nt][2] + b0, 0.0f) * a8;
            colsum[nt][1] += fmaxf(acc[mt][nt][1] + b1, 0.0f) * a0
                           + fmaxf(acc[mt][nt][3] + b1, 0.0f) * a8;
        }
    }
    #pragma unroll
    for (int nt = 0; nt < 4; ++nt) {
        #pragma unroll
        for (int j = 0; j < 2; ++j) {
            float v = colsum[nt][j];
            v += __shfl_down_sync(0xffffffffu, v, 16);
            v += __shfl_down_sync(0xffffffffu, v, 8);
            v += __shfl_down_sync(0xffffffffu, v, 4);
            if (lane < 4)
                sred[wm * 256 + nb + nt * 8 + 2 * lane + j] = v;
        }
    }
    __syncthreads();   // both wm halves in sred
    if (tid < HIDF)
        g_partials[(size_t)blockIdx.x * HIDF + tid] = sred[tid] + sred[256 + tid];
}

// ---- parallel tail: 32-way partial reduce, h MLP, output MLP ----------------
__global__ void red_kernel(int R) {
    int t = threadIdx.x, b = blockIdx.x;
    float s = 0.0f;
    for (int r = b; r < R; r += 32) s += g_partials[(size_t)r * HIDF + t];
    g_p2[b * HIDF + t] = s;
}
__global__ void h_kernel(const float* __restrict__ We2n, const float* __restrict__ be2n) {
    __shared__ float s[HIDF];
    int t = threadIdx.x, w = t >> 5, lane = t & 31;
    float a = 0.0f;
    #pragma unroll
    for (int b = 0; b < 32; ++b) a += g_p2[b * HIDF + t];
    s[t] = a;
    __syncthreads();
    int row = blockIdx.x * 8 + w;
    const float* wr = We2n + row * HIDF;
    float acc = 0.0f;
    #pragma unroll
    for (int i = 0; i < 8; ++i) acc += wr[lane + 32 * i] * s[lane + 32 * i];
    #pragma unroll
    for (int o = 16; o >= 1; o >>= 1) acc += __shfl_down_sync(0xffffffffu, acc, o);
    if (lane == 0) g_h[row] = acc + be2n[row];
}
__global__ void final_kernel(const float* __restrict__ Wout, const float* __restrict__ bout,
                             float* __restrict__ out) {
    __shared__ float v[DIMF + HIDF];
    int t = threadIdx.x, w = t >> 5, lane = t & 31;
    for (int i = t; i < DIMF + HIDF; i += 256)
        v[i] = (i < DIMF) ? g_xi[i] : g_h[i - DIMF];
    __syncthreads();
    #pragma unroll
    for (int it = 0; it < 4; ++it) {
        int row = blockIdx.x * 32 + w * 4 + it;
        const float* wr = Wout + row * (DIMF + HIDF);
        float acc = 0.0f;
        #pragma unroll
        for (int i = 0; i < 12; ++i) acc += wr[lane + 32 * i] * v[lane + 32 * i];
        #pragma unroll
        for (int o = 16; o >= 1; o >>= 1) acc += __shfl_down_sync(0xffffffffu, acc, o);
        if (lane == 0) out[row] = v[row] + acc + bout[row];
    }
}

extern "C" void kernel_launch(void* const* d_in, const int* in_sizes, int n_in,
                              void* d_out, int out_size) {
    const float* x    = (const float*)d_in[0];
    const float* adj  = (const float*)d_in[1];
    const int*   ip   = (const int*)  d_in[2];
    const float* Wn2e = (const float*)d_in[3];
    const float* bn2e = (const float*)d_in[4];
    const float* We2e = (const float*)d_in[5];
    const float* be2e = (const float*)d_in[6];
    const float* We2n = (const float*)d_in[7];
    const float* be2n = (const float*)d_in[8];
    const float* Wout = (const float*)d_in[9];
    const float* bout = (const float*)d_in[10];
    float* out = (float*)d_out;

    const int N = in_sizes[1];
    const int nblk = (N + TM - 1) / TM;
    const int dyn = (128 * H1S + 2 * 512 * BSTR) * 2;   // 149,504 bytes
    cudaFuncSetAttribute(main_kernel, cudaFuncAttributeMaxDynamicSharedMemorySize, dyn);

    prep_kernel<<<481, 256>>>(x, ip, Wn2e, bn2e, We2e);
    main_kernel<<<nblk, 512, dyn>>>(x, adj, be2e, N);
    red_kernel<<<32, 256>>>(nblk);
    h_kernel<<<32, 256>>>(We2n, be2n);
    final_kernel<<<4, 256>>>(Wout, bout, out);
}